// round 6
// baseline (speedup 1.0000x reference)
#include <cuda_runtime.h>
#include <cuda_fp16.h>
#include <cstdint>

// Layout after transpose: g_buf[n][plane][frame] in HALF precision.
// plane 0 = x, plane 1 = y, 64 frames contiguous (2B each).
// Per point: 2 planes * 64 frames * 2B = 256 bytes. Plane row = 128B.
#define MAX_N 100000
__device__ __align__(256) __half2 g_buf[(size_t)MAX_N * 64];
__device__ int g_is64;

// ---------------- helpers ----------------
__device__ __forceinline__ unsigned long long fma2(unsigned long long a,
                                                   unsigned long long b,
                                                   unsigned long long c) {
    unsigned long long r;
    asm("fma.rn.f32x2 %0, %1, %2, %3;" : "=l"(r) : "l"(a), "l"(b), "l"(c));
    return r;
}
__device__ __forceinline__ void upk(unsigned long long v, float& a, float& b) {
    asm("mov.b64 {%0, %1}, %2;" : "=f"(a), "=f"(b) : "l"(v));
}
__device__ __forceinline__ unsigned long long pk(float a, float b) {
    unsigned long long r;
    asm("mov.b64 %0, {%1, %2};" : "=l"(r) : "f"(a), "f"(b));
    return r;
}
__device__ __forceinline__ float sqapx(float x) {
    float r;
    asm("sqrt.approx.f32 %0, %1;" : "=f"(r) : "f"(x));
    return r;
}
__device__ __forceinline__ void cp_async16(unsigned dst, const void* src) {
    asm volatile("cp.async.cg.shared.global [%0], [%1], 16;"
                 :: "r"(dst), "l"(src) : "memory");
}
__device__ __forceinline__ uint4 lds128(unsigned addr) {
    uint4 v;
    asm volatile("ld.shared.v4.u32 {%0,%1,%2,%3}, [%4];"
                 : "=r"(v.x), "=r"(v.y), "=r"(v.z), "=r"(v.w) : "r"(addr));
    return v;
}

// ---------------- Kernel 1: transpose [64, N] float2 -> half [N][2][64] ----
__global__ void __launch_bounds__(256) transpose_kernel(
    const float2* __restrict__ in, const unsigned* __restrict__ skel_raw,
    float* out, int N) {
    if (blockIdx.x == 0 && threadIdx.x < 32) {
        unsigned v = skel_raw[2 * threadIdx.x + 1] | skel_raw[2 * (threadIdx.x + 32) + 1];
        unsigned b = __ballot_sync(0xffffffffu, v == 0u);
        if (threadIdx.x == 0) {
            g_is64 = (b == 0xffffffffu);
            out[0] = 0.0f;
        }
    }

    __shared__ float2 tile[64][33];
    int n0 = blockIdx.x * 32;
    int tx = threadIdx.x & 31;
    int ty = threadIdx.x >> 5;
    int c = n0 + tx;
    if (c < N) {
#pragma unroll
        for (int i = 0; i < 8; ++i) {
            int b = ty + i * 8;
            tile[b][tx] = __ldcs(&in[(size_t)b * N + c]);
        }
    }
    __syncthreads();
#pragma unroll
    for (int k = 0; k < 4; ++k) {
        int l = threadIdx.x + k * 256;
        int bp = l & 31;
        int cc = l >> 5;
        int n = n0 + cc;
        if (n < N) {
            float2 v0 = tile[2 * bp][cc];
            float2 v1 = tile[2 * bp + 1][cc];
            g_buf[(size_t)n * 64 + bp]      = __floats2half2_rn(v0.x, v1.x);
            g_buf[(size_t)n * 64 + 32 + bp] = __floats2half2_rn(v0.y, v1.y);
        }
    }
}

// ---------------- Kernel 2: main loss ----------------
// Warp = 4 edges (8 lanes each); lane covers 8 frames. Gathers staged into
// smem via cp.async (LDGSTS) with a 2-deep per-warp pipeline: registers hold
// only indices, so 6 blocks/SM fit. Each thread reads back only its own
// cp.async data -> no barrier, just cp.async.wait_group.

struct Quad { int s0, s1; float c; };

__device__ __forceinline__ Quad load_idx(const void* skel_raw,
                                         const float* init_len,
                                         int e, int E, bool is64) {
    Quad q;
    int ec = e < E ? e : (E - 1);
    if (is64) {
        longlong2 s = ((const longlong2*)skel_raw)[ec];
        q.s0 = (int)s.x;
        q.s1 = (int)s.y;
    } else {
        int2 s = ((const int2*)skel_raw)[ec];
        q.s0 = s.x;
        q.s1 = s.y;
    }
    q.c = init_len[ec];
    if (e >= E) { q.s0 = 0; q.s1 = 0; q.c = 0.0f; }
    return q;
}

// stage layout within a warp's 2KB stage: plane j (ax,ay,bx,by) * 512B + lane*16
__device__ __forceinline__ void issue_gather(unsigned stage_addr, const char* tb,
                                             Quad q, int lane) {
    unsigned d = stage_addr + lane * 16;
    const char* p0 = tb + (size_t)q.s0 * 256;
    const char* p1 = tb + (size_t)q.s1 * 256;
    cp_async16(d,        p0);        // ax
    cp_async16(d + 512,  p0 + 128);  // ay
    cp_async16(d + 1024, p1);        // bx
    cp_async16(d + 1536, p1 + 128);  // by
    asm volatile("cp.async.commit_group;" ::: "memory");
}

__global__ void __launch_bounds__(256, 6) loss_kernel(
    const void* __restrict__ skel_raw, const float* __restrict__ init_len,
    float* out, int E, float invE) {
    __shared__ __align__(16) char stages[8][2][2048];  // [warp][stage] 32KB
    __shared__ float warp_sums[8];

    const unsigned long long NEG1 = 0xBF800000BF800000ULL;
    int lane = threadIdx.x & 31;
    int wid = threadIdx.x >> 5;
    int quarter = lane >> 3;
    int el = lane & 7;
    int warp = (blockIdx.x * blockDim.x + threadIdx.x) >> 5;
    int nwarps = (gridDim.x * blockDim.x) >> 5;
    int P = (E + 3) >> 2;
    bool is64 = (g_is64 != 0);
    const char* tb = (const char*)g_buf + (size_t)el * 16;

    unsigned sbase = (unsigned)__cvta_generic_to_shared(&stages[wid][0][0]);

    unsigned long long acc = 0ull;

    // Prologue: stage 0 in flight for quad p; indices for p+nwarps resident.
    int p = warp;
    Quad q_cur = load_idx(skel_raw, init_len, 4 * p + quarter, E, is64);
    issue_gather(sbase, tb, q_cur, lane);
    Quad q_nxt = load_idx(skel_raw, init_len, 4 * (p + nwarps) + quarter, E, is64);

    unsigned s = 0;  // current compute stage offset (0 or 2048)
    for (; p < P; p += nwarps) {
        // Issue next stage's gathers (indices already resident).
        issue_gather(sbase + (s ^ 2048u), tb, q_nxt, lane);
        // Load indices two iterations ahead (overlaps with everything).
        Quad q_fut = load_idx(skel_raw, init_len,
                              4 * (p + 2 * nwarps) + quarter, E, is64);

        // Wait for current stage (allow the just-issued group to stay pending).
        asm volatile("cp.async.wait_group 1;" ::: "memory");

        unsigned a = sbase + s + lane * 16;
        uint4 ax = lds128(a);
        uint4 ay = lds128(a + 512);
        uint4 bx = lds128(a + 1024);
        uint4 by = lds128(a + 1536);

        unsigned long long cc2 = pk(q_cur.c, q_cur.c);
        const __half2* axh = (const __half2*)&ax;
        const __half2* ayh = (const __half2*)&ay;
        const __half2* bxh = (const __half2*)&bx;
        const __half2* byh = (const __half2*)&by;
#pragma unroll
        for (int i = 0; i < 4; ++i) {
            __half2 dx = __hsub2(axh[i], bxh[i]);
            __half2 dy = __hsub2(ayh[i], byh[i]);
            __half2 t = __hfma2(dy, dy, __hmul2(dx, dx));
            float2 tf = __half22float2(t);
            unsigned long long len = pk(sqapx(tf.x), sqapx(tf.y));
            unsigned long long d = fma2(cc2, NEG1, len);
            acc = fma2(d, d, acc);
        }

        q_cur = q_nxt;
        q_nxt = q_fut;
        s ^= 2048u;
    }

    float a0, a1;
    upk(acc, a0, a1);
    float sum = a0 + a1;
#pragma unroll
    for (int off = 16; off; off >>= 1)
        sum += __shfl_down_sync(0xffffffffu, sum, off);

    if (lane == 0) warp_sums[wid] = sum;
    __syncthreads();
    if (threadIdx.x < 8) {
        float v = warp_sums[threadIdx.x];
#pragma unroll
        for (int off = 4; off; off >>= 1)
            v += __shfl_down_sync(0xffu, v, off);
        if (threadIdx.x == 0) atomicAdd(out, v * invE);
    }
}

extern "C" void kernel_launch(void* const* d_in, const int* in_sizes, int n_in,
                              void* d_out, int out_size) {
    const float2* pts = (const float2*)d_in[0];
    const void* skel = d_in[1];
    const float* initl = (const float*)d_in[2];
    float* out = (float*)d_out;

    int N = in_sizes[0] / 128;  // B=64 frames, 2 coords
    int E = in_sizes[2];

    transpose_kernel<<<(N + 31) / 32, 256>>>(pts, (const unsigned*)skel, out, N);
    loss_kernel<<<888, 256>>>(skel, initl, out, E, 1.0f / (float)E);
}

// round 7
// speedup vs baseline: 1.7840x; 1.7840x over previous
#include <cuda_runtime.h>
#include <cuda_fp16.h>
#include <cstdint>

// Layout after transpose: g_buf[n][plane][frame] in HALF precision.
// plane 0 = x, plane 1 = y, 64 frames contiguous (2B each).
// Per point: 2 planes * 64 frames * 2B = 256 bytes. Plane row = 128B.
#define MAX_N 100000
__device__ __align__(256) __half2 g_buf[(size_t)MAX_N * 64];
__device__ int g_is64;

// ---------------- f32x2 / sqrt.approx helpers ----------------
__device__ __forceinline__ unsigned long long fma2(unsigned long long a,
                                                   unsigned long long b,
                                                   unsigned long long c) {
    unsigned long long r;
    asm("fma.rn.f32x2 %0, %1, %2, %3;" : "=l"(r) : "l"(a), "l"(b), "l"(c));
    return r;
}
__device__ __forceinline__ void upk(unsigned long long v, float& a, float& b) {
    asm("mov.b64 {%0, %1}, %2;" : "=f"(a), "=f"(b) : "l"(v));
}
__device__ __forceinline__ unsigned long long pk(float a, float b) {
    unsigned long long r;
    asm("mov.b64 %0, {%1, %2};" : "=l"(r) : "f"(a), "f"(b));
    return r;
}
__device__ __forceinline__ float sqapx(float x) {
    float r;
    asm("sqrt.approx.f32 %0, %1;" : "=f"(r) : "f"(x));
    return r;
}

// ---------------- Kernel 1: transpose [64, N] float2 -> half [N][2][64] ----
// Block 0 additionally: detect skeleton dtype (int64 vs int32) via parallel
// ballot, and zero the output scalar. Input reads evict-first to protect
// g_buf's L2 residency.
__global__ void __launch_bounds__(256) transpose_kernel(
    const float2* __restrict__ in, const unsigned* __restrict__ skel_raw,
    float* out, int N) {
    if (blockIdx.x == 0 && threadIdx.x < 32) {
        unsigned v = skel_raw[2 * threadIdx.x + 1] | skel_raw[2 * (threadIdx.x + 32) + 1];
        unsigned b = __ballot_sync(0xffffffffu, v == 0u);
        if (threadIdx.x == 0) {
            g_is64 = (b == 0xffffffffu);
            out[0] = 0.0f;
        }
    }

    __shared__ float2 tile[64][33];
    int n0 = blockIdx.x * 32;
    int tx = threadIdx.x & 31;
    int ty = threadIdx.x >> 5;
    int c = n0 + tx;
    if (c < N) {
#pragma unroll
        for (int i = 0; i < 8; ++i) {
            int b = ty + i * 8;  // frame index 0..63
            tile[b][tx] = __ldcs(&in[(size_t)b * N + c]);
        }
    }
    __syncthreads();
#pragma unroll
    for (int k = 0; k < 4; ++k) {
        int l = threadIdx.x + k * 256;
        int bp = l & 31;      // frame pair: frames 2bp, 2bp+1
        int cc = l >> 5;      // point within block
        int n = n0 + cc;
        if (n < N) {
            float2 v0 = tile[2 * bp][cc];
            float2 v1 = tile[2 * bp + 1][cc];
            g_buf[(size_t)n * 64 + bp]      = __floats2half2_rn(v0.x, v1.x);  // x plane
            g_buf[(size_t)n * 64 + 32 + bp] = __floats2half2_rn(v0.y, v1.y);  // y plane
        }
    }
}

// ---------------- Kernel 2: main loss ----------------
// Warp = 2 edges (16 lanes each). Lane handles 4 frames: one uint2 (8B =
// 4 halves = 2 half2) per plane per endpoint. Depth-2 register pipeline of
// the gathers (8 regs/stage), single-ahead index prefetch. ~46 regs ->
// 5 blocks/SM (40 warps). Inner math native half2; f32 from sqrt on.
// Tail branch-free: e >= E clamped to s0=s1=0, c=0 => contributes 0.

struct Pair { int s0, s1; float c; };
struct GatherH { uint2 ax, ay, bx, by; };  // 8 regs

__device__ __forceinline__ Pair load_idx(const void* skel_raw,
                                         const float* init_len,
                                         int e, int E, bool is64) {
    Pair q;
    int ec = e < E ? e : (E - 1);
    if (is64) {
        longlong2 s = ((const longlong2*)skel_raw)[ec];
        q.s0 = (int)s.x;
        q.s1 = (int)s.y;
    } else {
        int2 s = ((const int2*)skel_raw)[ec];
        q.s0 = s.x;
        q.s1 = s.y;
    }
    q.c = init_len[ec];
    if (e >= E) { q.s0 = 0; q.s1 = 0; q.c = 0.0f; }
    return q;
}

__device__ __forceinline__ GatherH issue_gather(const char* tb, Pair q) {
    GatherH g;
    const char* p0 = tb + (size_t)q.s0 * 256;
    const char* p1 = tb + (size_t)q.s1 * 256;
    g.ax = *(const uint2*)(p0);          // x halves, endpoint 0 (frames 4el..4el+3)
    g.ay = *(const uint2*)(p0 + 128);    // y halves
    g.bx = *(const uint2*)(p1);
    g.by = *(const uint2*)(p1 + 128);
    return g;
}

__global__ void __launch_bounds__(256, 5) loss_kernel(
    const void* __restrict__ skel_raw, const float* __restrict__ init_len,
    float* out, int E, float invE) {
    const unsigned long long NEG1 = 0xBF800000BF800000ULL;  // (-1.f, -1.f)
    int lane = threadIdx.x & 31;
    int half = lane >> 4;      // which of 2 edges in warp
    int el = lane & 15;        // lane within edge: frames 4*el .. 4*el+3
    int warp = (blockIdx.x * blockDim.x + threadIdx.x) >> 5;
    int nwarps = (gridDim.x * blockDim.x) >> 5;
    int P = (E + 1) >> 1;
    bool is64 = (g_is64 != 0);
    const char* tb = (const char*)g_buf + (size_t)el * 8;

    unsigned long long acc = 0ull;

    // Prologue: indices + gathers for p; indices for p+nwarps.
    int p = warp;
    Pair qc = load_idx(skel_raw, init_len, 2 * p + half, E, is64);
    GatherH gc = issue_gather(tb, qc);
    Pair qn = load_idx(skel_raw, init_len, 2 * (p + nwarps) + half, E, is64);

    for (; p < P; p += nwarps) {
        // Issue next iteration's gathers (indices already resident).
        GatherH gn = issue_gather(tb, qn);
        // Load indices for the iteration after next.
        Pair qf = load_idx(skel_raw, init_len,
                           2 * (p + 2 * nwarps) + half, E, is64);

        // Compute on current gathers (in flight since previous iteration).
        unsigned long long cc2 = pk(qc.c, qc.c);
        const __half2* axh = (const __half2*)&gc.ax;
        const __half2* ayh = (const __half2*)&gc.ay;
        const __half2* bxh = (const __half2*)&gc.bx;
        const __half2* byh = (const __half2*)&gc.by;
#pragma unroll
        for (int i = 0; i < 2; ++i) {
            __half2 dx = __hsub2(axh[i], bxh[i]);
            __half2 dy = __hsub2(ayh[i], byh[i]);
            __half2 t = __hfma2(dy, dy, __hmul2(dx, dx));
            float2 tf = __half22float2(t);
            unsigned long long len = pk(sqapx(tf.x), sqapx(tf.y));
            unsigned long long d = fma2(cc2, NEG1, len);
            acc = fma2(d, d, acc);
        }

        qc = qn;
        qn = qf;
        gc = gn;
    }

    float a0, a1;
    upk(acc, a0, a1);
    float s = a0 + a1;
#pragma unroll
    for (int off = 16; off; off >>= 1)
        s += __shfl_down_sync(0xffffffffu, s, off);

    __shared__ float warp_sums[8];
    if (lane == 0) warp_sums[threadIdx.x >> 5] = s;
    __syncthreads();
    if (threadIdx.x < 8) {
        float v = warp_sums[threadIdx.x];
#pragma unroll
        for (int off = 4; off; off >>= 1)
            v += __shfl_down_sync(0xffu, v, off);
        if (threadIdx.x == 0) atomicAdd(out, v * invE);
    }
}

extern "C" void kernel_launch(void* const* d_in, const int* in_sizes, int n_in,
                              void* d_out, int out_size) {
    const float2* pts = (const float2*)d_in[0];
    const void* skel = d_in[1];
    const float* initl = (const float*)d_in[2];
    float* out = (float*)d_out;

    int N = in_sizes[0] / 128;  // B=64 frames, 2 coords
    int E = in_sizes[2];

    transpose_kernel<<<(N + 31) / 32, 256>>>(pts, (const unsigned*)skel, out, N);
    loss_kernel<<<740, 256>>>(skel, initl, out, E, 1.0f / (float)E);
}

// round 8
// speedup vs baseline: 1.8014x; 1.0097x over previous
#include <cuda_runtime.h>
#include <cuda_fp16.h>
#include <cstdint>

// Layout after transpose: per point n, 256 bytes = 16 chunks of 16B.
// Chunk f (f=0..15) = [ x(4f), x(4f+1), x(4f+2), x(4f+3),
//                       y(4f), y(4f+1), y(4f+2), y(4f+3) ]  (8 halves).
// One edge endpoint = one contiguous 256B row = one LDG.128 across 16 lanes.
#define MAX_N 100000
__device__ __align__(256) __half2 g_buf[(size_t)MAX_N * 64];
__device__ int g_is64;

// ---------------- f32x2 / sqrt.approx helpers ----------------
__device__ __forceinline__ unsigned long long fma2(unsigned long long a,
                                                   unsigned long long b,
                                                   unsigned long long c) {
    unsigned long long r;
    asm("fma.rn.f32x2 %0, %1, %2, %3;" : "=l"(r) : "l"(a), "l"(b), "l"(c));
    return r;
}
__device__ __forceinline__ void upk(unsigned long long v, float& a, float& b) {
    asm("mov.b64 {%0, %1}, %2;" : "=f"(a), "=f"(b) : "l"(v));
}
__device__ __forceinline__ unsigned long long pk(float a, float b) {
    unsigned long long r;
    asm("mov.b64 %0, {%1, %2};" : "=l"(r) : "f"(a), "f"(b));
    return r;
}
__device__ __forceinline__ float sqapx(float x) {
    float r;
    asm("sqrt.approx.f32 %0, %1;" : "=f"(r) : "f"(x));
    return r;
}

// ---------------- Kernel 1: transpose [64, N] float2 -> chunked half ----
// Block 0 additionally: detect skeleton dtype (int64 vs int32) via parallel
// ballot, and zero the output scalar.
__global__ void __launch_bounds__(256) transpose_kernel(
    const float2* __restrict__ in, const unsigned* __restrict__ skel_raw,
    float* out, int N) {
    if (blockIdx.x == 0 && threadIdx.x < 32) {
        unsigned v = skel_raw[2 * threadIdx.x + 1] | skel_raw[2 * (threadIdx.x + 32) + 1];
        unsigned b = __ballot_sync(0xffffffffu, v == 0u);
        if (threadIdx.x == 0) {
            g_is64 = (b == 0xffffffffu);
            out[0] = 0.0f;
        }
    }

    __shared__ float2 tile[64][33];
    int n0 = blockIdx.x * 32;
    int tx = threadIdx.x & 31;
    int ty = threadIdx.x >> 5;
    int c = n0 + tx;
    if (c < N) {
#pragma unroll
        for (int i = 0; i < 8; ++i) {
            int b = ty + i * 8;  // frame index 0..63
            tile[b][tx] = __ldcs(&in[(size_t)b * N + c]);
        }
    }
    __syncthreads();
#pragma unroll
    for (int k = 0; k < 4; ++k) {
        int l = threadIdx.x + k * 256;
        int bp = l & 31;      // frame pair: frames 2bp, 2bp+1
        int cc = l >> 5;      // point within block
        int n = n0 + cc;
        if (n < N) {
            float2 v0 = tile[2 * bp][cc];
            float2 v1 = tile[2 * bp + 1][cc];
            // chunk index f = bp>>1; half2 slot within chunk = bp&1
            char* base = (char*)g_buf + (size_t)n * 256 + (bp >> 1) * 16 + (bp & 1) * 4;
            *(__half2*)(base)     = __floats2half2_rn(v0.x, v1.x);  // x pair
            *(__half2*)(base + 8) = __floats2half2_rn(v0.y, v1.y);  // y pair
        }
    }
}

// ---------------- Kernel 2: main loss ----------------
// Warp = 2 edges (16 lanes each). Lane covers 4 frames via ONE uint4 (16B
// chunk: x-pair, x-pair, y-pair, y-pair) per endpoint => 2 LDG.128 per
// warp-iter. Depth-2 register pipeline of gathers (8 regs/stage), indices
// prefetched two ahead. Inner math native half2; f32 from sqrt on.
// Tail branch-free: e >= E clamped to s0=s1=0, c=0 => contributes 0.

struct Pair { int s0, s1; float c; };
struct GatherC { uint4 a, b; };  // 8 regs

__device__ __forceinline__ Pair load_idx(const void* skel_raw,
                                         const float* init_len,
                                         int e, int E, bool is64) {
    Pair q;
    int ec = e < E ? e : (E - 1);
    if (is64) {
        longlong2 s = ((const longlong2*)skel_raw)[ec];
        q.s0 = (int)s.x;
        q.s1 = (int)s.y;
    } else {
        int2 s = ((const int2*)skel_raw)[ec];
        q.s0 = s.x;
        q.s1 = s.y;
    }
    q.c = init_len[ec];
    if (e >= E) { q.s0 = 0; q.s1 = 0; q.c = 0.0f; }
    return q;
}

__device__ __forceinline__ GatherC issue_gather(const char* tb, Pair q) {
    GatherC g;
    g.a = *(const uint4*)(tb + (unsigned)q.s0 * 256u);
    g.b = *(const uint4*)(tb + (unsigned)q.s1 * 256u);
    return g;
}

__global__ void __launch_bounds__(256, 6) loss_kernel(
    const void* __restrict__ skel_raw, const float* __restrict__ init_len,
    float* out, int E, float invE) {
    const unsigned long long NEG1 = 0xBF800000BF800000ULL;  // (-1.f, -1.f)
    int lane = threadIdx.x & 31;
    int half = lane >> 4;      // which of 2 edges in warp
    int el = lane & 15;        // chunk index within row
    int warp = (blockIdx.x * blockDim.x + threadIdx.x) >> 5;
    int nwarps = (gridDim.x * blockDim.x) >> 5;
    int P = (E + 1) >> 1;
    bool is64 = (g_is64 != 0);
    const char* tb = (const char*)g_buf + (unsigned)el * 16u;

    unsigned long long acc = 0ull;

    // Prologue: indices + gathers for p; indices for p+nwarps.
    int p = warp;
    Pair qc = load_idx(skel_raw, init_len, 2 * p + half, E, is64);
    GatherC gc = issue_gather(tb, qc);
    Pair qn = load_idx(skel_raw, init_len, 2 * (p + nwarps) + half, E, is64);

    for (; p < P; p += nwarps) {
        // Issue next iteration's gathers (indices already resident).
        GatherC gn = issue_gather(tb, qn);
        // Load indices for the iteration after next.
        Pair qf = load_idx(skel_raw, init_len,
                           2 * (p + 2 * nwarps) + half, E, is64);

        // Compute on current gathers (in flight since previous iteration).
        unsigned long long cc2 = pk(qc.c, qc.c);
        const __half2* A = (const __half2*)&gc.a;  // [x01, x23, y01, y23]
        const __half2* B = (const __half2*)&gc.b;
        __half2 dx01 = __hsub2(A[0], B[0]);
        __half2 dx23 = __hsub2(A[1], B[1]);
        __half2 dy01 = __hsub2(A[2], B[2]);
        __half2 dy23 = __hsub2(A[3], B[3]);
        __half2 t01 = __hfma2(dy01, dy01, __hmul2(dx01, dx01));
        __half2 t23 = __hfma2(dy23, dy23, __hmul2(dx23, dx23));
        float2 f01 = __half22float2(t01);
        float2 f23 = __half22float2(t23);
        unsigned long long len0 = pk(sqapx(f01.x), sqapx(f01.y));
        unsigned long long len1 = pk(sqapx(f23.x), sqapx(f23.y));
        unsigned long long d0 = fma2(cc2, NEG1, len0);
        unsigned long long d1 = fma2(cc2, NEG1, len1);
        acc = fma2(d0, d0, acc);
        acc = fma2(d1, d1, acc);

        qc = qn;
        qn = qf;
        gc = gn;
    }

    float a0, a1;
    upk(acc, a0, a1);
    float s = a0 + a1;
#pragma unroll
    for (int off = 16; off; off >>= 1)
        s += __shfl_down_sync(0xffffffffu, s, off);

    __shared__ float warp_sums[8];
    if (lane == 0) warp_sums[threadIdx.x >> 5] = s;
    __syncthreads();
    if (threadIdx.x < 8) {
        float v = warp_sums[threadIdx.x];
#pragma unroll
        for (int off = 4; off; off >>= 1)
            v += __shfl_down_sync(0xffu, v, off);
        if (threadIdx.x == 0) atomicAdd(out, v * invE);
    }
}

extern "C" void kernel_launch(void* const* d_in, const int* in_sizes, int n_in,
                              void* d_out, int out_size) {
    const float2* pts = (const float2*)d_in[0];
    const void* skel = d_in[1];
    const float* initl = (const float*)d_in[2];
    float* out = (float*)d_out;

    int N = in_sizes[0] / 128;  // B=64 frames, 2 coords
    int E = in_sizes[2];

    transpose_kernel<<<(N + 31) / 32, 256>>>(pts, (const unsigned*)skel, out, N);
    loss_kernel<<<888, 256>>>(skel, initl, out, E, 1.0f / (float)E);
}